// round 5
// baseline (speedup 1.0000x reference)
#include <cuda_runtime.h>
#include <cstdint>

#define NN   100000
#define NE   1600000
#define DIN  128
#define DH   128
#define DOUT 64

// -------- scratch (device globals: allocation-guard safe) --------
__device__ float g_g1[(size_t)NN * DH];    // feat @ W1
__device__ float g_n1[(size_t)NN * DH];    // segsum of g1 over edges
__device__ float g_g2[(size_t)NN * DOUT];  // h1 @ W2
__device__ float g_n2[(size_t)NN * DOUT];  // segsum of g2 over edges
__device__ float g_deg[NN];

// -------- packed fp32x2 helpers (Blackwell FFMA2 path) --------
__device__ __forceinline__ unsigned long long pack2(float x) {
    unsigned long long r;
    asm("mov.b64 %0, {%1, %1};" : "=l"(r) : "r"(__float_as_uint(x)));
    return r;
}
__device__ __forceinline__ unsigned long long fma2(unsigned long long a,
                                                   unsigned long long b,
                                                   unsigned long long c) {
    unsigned long long d;
    asm("fma.rn.f32x2 %0, %1, %2, %3;" : "=l"(d) : "l"(a), "l"(b), "l"(c));
    return d;
}

// =================== kernels ===================

__global__ void zero_kernel() {
    size_t stride = (size_t)gridDim.x * blockDim.x;
    size_t i0 = (size_t)blockIdx.x * blockDim.x + threadIdx.x;
    float4 z = make_float4(0.f, 0.f, 0.f, 0.f);
    float4* n1 = (float4*)g_n1;
    for (size_t i = i0; i < (size_t)NN * DH / 4; i += stride) n1[i] = z;
    float4* n2 = (float4*)g_n2;
    for (size_t i = i0; i < (size_t)NN * DOUT / 4; i += stride) n2[i] = z;
    for (size_t i = i0; i < NN; i += stride) g_deg[i] = 0.f;
}

__global__ void deg_kernel(const int* __restrict__ dst) {
    int stride = gridDim.x * blockDim.x;
    for (int i = blockIdx.x * blockDim.x + threadIdx.x; i < NE; i += stride)
        atomicAdd(&g_deg[dst[i]], 1.0f);  // no return -> RED
}

// g1 = feat @ W1   (M=NN, N=128, K=128), fp32, no bias here.
// 256 threads, 64-node tile. W1 (64KB) + padded x tile (33KB) in smem.
__global__ void gemm1_kernel(const float* __restrict__ feat,
                             const float* __restrict__ W1) {
    extern __shared__ float sm[];
    float* Ws = sm;               // 128*128
    float* xs = sm + DIN * DH;    // 64*129 (pad -> bank (n+k)%32)
    const int tid = threadIdx.x;

    {   // stage W1: 4096 float4 / 256 threads
        const float4* w4 = (const float4*)W1;
        float4* ws4 = (float4*)Ws;
#pragma unroll
        for (int i = 0; i < 16; i++) ws4[tid + 256 * i] = w4[tid + 256 * i];
    }
    const int m0 = blockIdx.x * 64;
    {   // stage x tile: 4 threads per node, 32 k-values each
        int nrow = tid >> 2;
        int kq = (tid & 3) << 5;
        int m = m0 + nrow;
        if (m < NN) {
            const float4* fr = (const float4*)(feat + (size_t)m * DIN);
#pragma unroll
            for (int j = 0; j < 8; j++) {
                float4 v = fr[(kq >> 2) + j];
                float* p = &xs[nrow * 129 + kq + 4 * j];
                p[0] = v.x; p[1] = v.y; p[2] = v.z; p[3] = v.w;
            }
        }
    }
    __syncthreads();

    const int n = tid & 63;       // node within tile (uniform q per warp)
    const int q = tid >> 6;       // column quarter: cols q*32 .. q*32+31
    const int m = m0 + n;
    unsigned long long acc[16];
#pragma unroll
    for (int j = 0; j < 16; j++) acc[j] = 0ull;

    const float* xrow = &xs[n * 129];
#pragma unroll 2
    for (int k = 0; k < DIN; k++) {
        unsigned long long xx = pack2(xrow[k]);
        const unsigned long long* w2 =
            (const unsigned long long*)(Ws + k * DH + q * 32);  // warp-uniform -> LDS broadcast
#pragma unroll
        for (int j = 0; j < 16; j++) acc[j] = fma2(xx, w2[j], acc[j]);
    }
    if (m < NN) {
        unsigned long long* o =
            (unsigned long long*)(g_g1 + (size_t)m * DH + q * 32);
#pragma unroll
        for (int j = 0; j < 16; j++) o[j] = acc[j];
    }
}

// scatter layer 1: n1[dst] += g1[src], 128 floats/edge, one warp per edge,
// lane carries one float4, RED.v4 at L2.
__global__ void scatter128_kernel(const int* __restrict__ src,
                                  const int* __restrict__ dst) {
    int gw = (blockIdx.x * blockDim.x + threadIdx.x) >> 5;
    int lane = threadIdx.x & 31;
    int nw = (gridDim.x * blockDim.x) >> 5;
    for (int e = gw; e < NE; e += nw) {
        int s = __ldg(src + e);
        int d = __ldg(dst + e);
        float4 v = ((const float4*)(g_g1 + (size_t)s * DH))[lane];
        float* p = g_n1 + (size_t)d * DH + lane * 4;
        asm volatile("red.global.add.v4.f32 [%0], {%1,%2,%3,%4};"
                     :: "l"(p), "f"(v.x), "f"(v.y), "f"(v.z), "f"(v.w)
                     : "memory");
    }
}

// fused: h1 = relu((n1 + g1) * 1/(deg+1) + b1);  g2 = h1 @ W2
// (h1 never materialized in GMEM)
__global__ void gemm2_kernel(const float* __restrict__ b1,
                             const float* __restrict__ W2) {
    extern __shared__ float sm[];
    float* Ws = sm;               // 128*64
    float* xs = sm + DH * DOUT;   // 64*129
    const int tid = threadIdx.x;

    {   // stage W2: 2048 float4
        const float4* w4 = (const float4*)W2;
        float4* ws4 = (float4*)Ws;
#pragma unroll
        for (int i = 0; i < 8; i++) ws4[tid + 256 * i] = w4[tid + 256 * i];
    }
    const int m0 = blockIdx.x * 64;
    {   // build h1 tile on the fly
        int nrow = tid >> 2;
        int kq = (tid & 3) << 5;
        int m = m0 + nrow;
        if (m < NN) {
            float inv = 1.0f / (g_deg[m] + 1.0f);
            const float4* a = (const float4*)(g_n1 + (size_t)m * DH);
            const float4* g = (const float4*)(g_g1 + (size_t)m * DH);
            const float4* bb = (const float4*)b1;
#pragma unroll
            for (int j = 0; j < 8; j++) {
                float4 va = a[(kq >> 2) + j];
                float4 vg = g[(kq >> 2) + j];
                float4 vb = bb[(kq >> 2) + j];
                float* p = &xs[nrow * 129 + kq + 4 * j];
                p[0] = fmaxf((va.x + vg.x) * inv + vb.x, 0.f);
                p[1] = fmaxf((va.y + vg.y) * inv + vb.y, 0.f);
                p[2] = fmaxf((va.z + vg.z) * inv + vb.z, 0.f);
                p[3] = fmaxf((va.w + vg.w) * inv + vb.w, 0.f);
            }
        }
    }
    __syncthreads();

    const int n = tid & 63;
    const int q = tid >> 6;       // cols q*16 .. q*16+15
    const int m = m0 + n;
    unsigned long long acc[8];
#pragma unroll
    for (int j = 0; j < 8; j++) acc[j] = 0ull;

    const float* xrow = &xs[n * 129];
#pragma unroll 2
    for (int k = 0; k < DH; k++) {
        unsigned long long xx = pack2(xrow[k]);
        const unsigned long long* w2 =
            (const unsigned long long*)(Ws + k * DOUT + q * 16);
#pragma unroll
        for (int j = 0; j < 8; j++) acc[j] = fma2(xx, w2[j], acc[j]);
    }
    if (m < NN) {
        unsigned long long* o =
            (unsigned long long*)(g_g2 + (size_t)m * DOUT + q * 16);
#pragma unroll
        for (int j = 0; j < 8; j++) o[j] = acc[j];
    }
}

// scatter layer 2: n2[dst] += g2[src], 64 floats/edge, lane carries float2.
__global__ void scatter64_kernel(const int* __restrict__ src,
                                 const int* __restrict__ dst) {
    int gw = (blockIdx.x * blockDim.x + threadIdx.x) >> 5;
    int lane = threadIdx.x & 31;
    int nw = (gridDim.x * blockDim.x) >> 5;
    for (int e = gw; e < NE; e += nw) {
        int s = __ldg(src + e);
        int d = __ldg(dst + e);
        float2 v = ((const float2*)(g_g2 + (size_t)s * DOUT))[lane];
        float* p = g_n2 + (size_t)d * DOUT + lane * 2;
        asm volatile("red.global.add.v2.f32 [%0], {%1,%2};"
                     :: "l"(p), "f"(v.x), "f"(v.y)
                     : "memory");
    }
}

// out = (n2 + g2) / (deg+1) + b2
__global__ void out_kernel(const float* __restrict__ b2,
                           float* __restrict__ out) {
    int stride = gridDim.x * blockDim.x;
    const float4* g2 = (const float4*)g_g2;
    const float4* n2 = (const float4*)g_n2;
    const float4* b = (const float4*)b2;
    float4* o = (float4*)out;
    const int total = NN * DOUT / 4;   // 16 float4 per row
    for (int i = blockIdx.x * blockDim.x + threadIdx.x; i < total; i += stride) {
        int node = i >> 4;
        int c = i & 15;
        float inv = 1.0f / (g_deg[node] + 1.0f);
        float4 a = n2[i], g = g2[i], bb = b[c];
        float4 r;
        r.x = (a.x + g.x) * inv + bb.x;
        r.y = (a.y + g.y) * inv + bb.y;
        r.z = (a.z + g.z) * inv + bb.z;
        r.w = (a.w + g.w) * inv + bb.w;
        o[i] = r;
    }
}

// =================== launch ===================
extern "C" void kernel_launch(void* const* d_in, const int* in_sizes, int n_in,
                              void* d_out, int out_size) {
    const float* feat = (const float*)d_in[0];
    const float* W1   = (const float*)d_in[1];
    const float* b1   = (const float*)d_in[2];
    const float* W2   = (const float*)d_in[3];
    const float* b2   = (const float*)d_in[4];
    const int*   src  = (const int*)d_in[5];
    const int*   dst  = (const int*)d_in[6];
    float* out = (float*)d_out;

    const int smem1 = (DIN * DH + 64 * 129) * (int)sizeof(float);   // 98,560 B
    const int smem2 = (DH * DOUT + 64 * 129) * (int)sizeof(float);  // 65,792 B
    cudaFuncSetAttribute(gemm1_kernel, cudaFuncAttributeMaxDynamicSharedMemorySize, smem1);
    cudaFuncSetAttribute(gemm2_kernel, cudaFuncAttributeMaxDynamicSharedMemorySize, smem2);

    const int gemm_blocks = (NN + 63) / 64;

    zero_kernel<<<1024, 256>>>();
    deg_kernel<<<1024, 256>>>(dst);
    gemm1_kernel<<<gemm_blocks, 256, smem1>>>(feat, W1);
    scatter128_kernel<<<2048, 256>>>(src, dst);
    gemm2_kernel<<<gemm_blocks, 256, smem2>>>(b1, W2);
    scatter64_kernel<<<2048, 256>>>(src, dst);
    out_kernel<<<2048, 256>>>(b2, out);
}

// round 6
// speedup vs baseline: 1.5113x; 1.5113x over previous
#include <cuda_runtime.h>
#include <cstdint>

#define NN   100000
#define NE   1600000
#define DIN  128
#define DH   128
#define DOUT 64
#define NBLK 98          // ceil(NN/1024)

// -------- scratch (device globals: allocation-guard safe) --------
__device__ float g_a1[(size_t)NN * DIN];   // (sum_neigh feat + feat)/(deg+1)
__device__ float g_g2[(size_t)NN * DOUT];  // h1 @ W2
__device__ int   g_cnt[NN];                // in-degree
__device__ int   g_rs[NN + 1];             // CSR row starts
__device__ int   g_cur[NN];                // scatter cursors
__device__ int   g_eord[NE];               // src ids sorted by dst
__device__ int   g_bsum[NBLK];
__device__ int   g_boff[NBLK];

// -------- packed fp32x2 helpers --------
__device__ __forceinline__ unsigned long long pack2(float x) {
    unsigned long long r;
    asm("mov.b64 %0, {%1, %1};" : "=l"(r) : "r"(__float_as_uint(x)));
    return r;
}
__device__ __forceinline__ unsigned long long fma2(unsigned long long a,
                                                   unsigned long long b,
                                                   unsigned long long c) {
    unsigned long long d;
    asm("fma.rn.f32x2 %0, %1, %2, %3;" : "=l"(d) : "l"(a), "l"(b), "l"(c));
    return d;
}

// =================== CSR build ===================

__global__ void zero_cnt_kernel() {
    int i = blockIdx.x * blockDim.x + threadIdx.x;
    if (i < NN) g_cnt[i] = 0;
}

__global__ void hist_kernel(const int* __restrict__ dst) {
    int stride = gridDim.x * blockDim.x;
    for (int i = blockIdx.x * blockDim.x + threadIdx.x; i < NE; i += stride)
        atomicAdd(&g_cnt[dst[i]], 1);   // no return -> RED
}

__global__ void scan_blocksums_kernel() {
    __shared__ int ws[32];
    int t = threadIdx.x, b = blockIdx.x;
    int i = b * 1024 + t;
    int v = (i < NN) ? g_cnt[i] : 0;
    int lane = t & 31, w = t >> 5;
    int x = v;
#pragma unroll
    for (int o = 16; o > 0; o >>= 1) x += __shfl_down_sync(~0u, x, o);
    if (lane == 0) ws[w] = x;
    __syncthreads();
    if (w == 0) {
        int y = ws[lane];
#pragma unroll
        for (int o = 16; o > 0; o >>= 1) y += __shfl_down_sync(~0u, y, o);
        if (lane == 0) g_bsum[b] = y;
    }
}

__global__ void scan_top_kernel() {
    __shared__ int s[NBLK];
    int t = threadIdx.x;
    if (t < NBLK) s[t] = g_bsum[t];
    __syncthreads();
    if (t == 0) {
        int run = 0;
        for (int i = 0; i < NBLK; i++) { int v = s[i]; s[i] = run; run += v; }
        g_rs[NN] = NE;
    }
    __syncthreads();
    if (t < NBLK) g_boff[t] = s[t];
}

__global__ void scan_final_kernel() {
    __shared__ int ws[32];
    int t = threadIdx.x, b = blockIdx.x;
    int i = b * 1024 + t;
    int v = (i < NN) ? g_cnt[i] : 0;
    int lane = t & 31, w = t >> 5;
    int x = v;
#pragma unroll
    for (int o = 1; o < 32; o <<= 1) {
        int y = __shfl_up_sync(~0u, x, o);
        if (lane >= o) x += y;
    }
    if (lane == 31) ws[w] = x;
    __syncthreads();
    if (w == 0) {
        int y = ws[lane];
#pragma unroll
        for (int o = 1; o < 32; o <<= 1) {
            int z = __shfl_up_sync(~0u, y, o);
            if (lane >= o) y += z;
        }
        ws[lane] = y;
    }
    __syncthreads();
    int incl = x + (w > 0 ? ws[w - 1] : 0);
    int excl = incl - v + g_boff[b];
    if (i < NN) { g_rs[i] = excl; g_cur[i] = excl; }
}

__global__ void permute_kernel(const int* __restrict__ src,
                               const int* __restrict__ dst) {
    int stride = gridDim.x * blockDim.x;
    for (int e = blockIdx.x * blockDim.x + threadIdx.x; e < NE; e += stride) {
        int d = dst[e];
        int p = atomicAdd(&g_cur[d], 1);
        g_eord[p] = src[e];
    }
}

// =================== layer 1 aggregate: one warp per dst node ===================
// a1[n] = (feat[n] + sum_{e: dst=n} feat[src_e]) / (deg_n + 1)
__global__ void spmm1_kernel(const float* __restrict__ feat) {
    int w = (blockIdx.x * blockDim.x + threadIdx.x) >> 5;
    int lane = threadIdx.x & 31;
    if (w >= NN) return;
    int beg = g_rs[w], end = g_rs[w + 1];
    const float4* f4 = (const float4*)feat;
    float4 acc = __ldg(&f4[w * 32 + lane]);   // self term
    int e = beg;
    for (; e + 4 <= end; e += 4) {
        int s0 = g_eord[e], s1 = g_eord[e + 1];
        int s2 = g_eord[e + 2], s3 = g_eord[e + 3];
        float4 v0 = __ldg(&f4[s0 * 32 + lane]);
        float4 v1 = __ldg(&f4[s1 * 32 + lane]);
        float4 v2 = __ldg(&f4[s2 * 32 + lane]);
        float4 v3 = __ldg(&f4[s3 * 32 + lane]);
        acc.x += (v0.x + v1.x) + (v2.x + v3.x);
        acc.y += (v0.y + v1.y) + (v2.y + v3.y);
        acc.z += (v0.z + v1.z) + (v2.z + v3.z);
        acc.w += (v0.w + v1.w) + (v2.w + v3.w);
    }
    for (; e < end; e++) {
        int s = g_eord[e];
        float4 v = __ldg(&f4[s * 32 + lane]);
        acc.x += v.x; acc.y += v.y; acc.z += v.z; acc.w += v.w;
    }
    float inv = 1.0f / (float)(end - beg + 1);
    acc.x *= inv; acc.y *= inv; acc.z *= inv; acc.w *= inv;
    ((float4*)g_a1)[w * 32 + lane] = acc;
}

// =================== fused GEMM: h1 = relu(a1@W1 + b1); g2 = h1@W2 ===============
// 64-node tile per block, 256 threads. smem: W1 (64KB) + W2 (32KB) + tile (33KB).
__global__ void gemm_fused_kernel(const float* __restrict__ W1,
                                  const float* __restrict__ b1,
                                  const float* __restrict__ W2) {
    extern __shared__ float sm[];
    float* W1s = sm;                       // 128*128
    float* W2s = sm + DIN * DH;            // 128*64
    float* xs  = W2s + DH * DOUT;          // 64*129
    const int tid = threadIdx.x;

    {   // stage W1, W2
        const float4* w4 = (const float4*)W1;
        float4* s4 = (float4*)W1s;
#pragma unroll
        for (int i = 0; i < 16; i++) s4[tid + 256 * i] = w4[tid + 256 * i];
        const float4* v4 = (const float4*)W2;
        float4* t4 = (float4*)W2s;
#pragma unroll
        for (int i = 0; i < 8; i++) t4[tid + 256 * i] = v4[tid + 256 * i];
    }
    const int m0 = blockIdx.x * 64;
    {   // stage a1 tile (already normalized)
        int nrow = tid >> 2;
        int kq = (tid & 3) << 5;
        int m = m0 + nrow;
        if (m < NN) {
            const float4* fr = (const float4*)(g_a1 + (size_t)m * DIN);
#pragma unroll
            for (int j = 0; j < 8; j++) {
                float4 v = fr[(kq >> 2) + j];
                float* p = &xs[nrow * 129 + kq + 4 * j];
                p[0] = v.x; p[1] = v.y; p[2] = v.z; p[3] = v.w;
            }
        }
    }
    __syncthreads();

    const int n = tid & 63;
    const int q = tid >> 6;      // phase 1: cols q*32..q*32+31
    const int m = m0 + n;

    // ---- phase 1: h1 cols for this thread ----
    unsigned long long acc[16];
#pragma unroll
    for (int j = 0; j < 16; j++) acc[j] = 0ull;
    {
        const float* xrow = &xs[n * 129];
#pragma unroll 2
        for (int k = 0; k < DIN; k++) {
            unsigned long long xx = pack2(xrow[k]);
            const float4* w4 = (const float4*)(W1s + k * DH + q * 32);
#pragma unroll
            for (int j = 0; j < 8; j++) {
                float4 wv = w4[j];
                unsigned long long w01, w23;
                asm("mov.b64 %0, {%1, %2};" : "=l"(w01)
                    : "r"(__float_as_uint(wv.x)), "r"(__float_as_uint(wv.y)));
                asm("mov.b64 %0, {%1, %2};" : "=l"(w23)
                    : "r"(__float_as_uint(wv.z)), "r"(__float_as_uint(wv.w)));
                acc[2 * j]     = fma2(xx, w01, acc[2 * j]);
                acc[2 * j + 1] = fma2(xx, w23, acc[2 * j + 1]);
            }
        }
    }
    __syncthreads();   // all warps done reading a1 tile; xs will hold h1

    {   // bias + relu, write h1 into xs (transposed-safe: stride-129 rows)
        const float* bb = b1 + q * 32;
        float* hrow = &xs[n * 129 + q * 32];
#pragma unroll
        for (int j = 0; j < 16; j++) {
            unsigned int lo = (unsigned int)(acc[j] & 0xffffffffull);
            unsigned int hi = (unsigned int)(acc[j] >> 32);
            float f0 = __uint_as_float(lo) + bb[2 * j];
            float f1 = __uint_as_float(hi) + bb[2 * j + 1];
            hrow[2 * j]     = fmaxf(f0, 0.0f);
            hrow[2 * j + 1] = fmaxf(f1, 0.0f);
        }
    }
    __syncthreads();

    // ---- phase 2: g2 = h1 @ W2; thread covers cols q*16..q*16+15 ----
    unsigned long long acc2[8];
#pragma unroll
    for (int j = 0; j < 8; j++) acc2[j] = 0ull;
    {
        const float* xrow = &xs[n * 129];
#pragma unroll 2
        for (int k = 0; k < DH; k++) {
            unsigned long long xx = pack2(xrow[k]);
            const float4* w4 = (const float4*)(W2s + k * DOUT + q * 16);
#pragma unroll
            for (int j = 0; j < 4; j++) {
                float4 wv = w4[j];
                unsigned long long w01, w23;
                asm("mov.b64 %0, {%1, %2};" : "=l"(w01)
                    : "r"(__float_as_uint(wv.x)), "r"(__float_as_uint(wv.y)));
                asm("mov.b64 %0, {%1, %2};" : "=l"(w23)
                    : "r"(__float_as_uint(wv.z)), "r"(__float_as_uint(wv.w)));
                acc2[2 * j]     = fma2(xx, w01, acc2[2 * j]);
                acc2[2 * j + 1] = fma2(xx, w23, acc2[2 * j + 1]);
            }
        }
    }
    if (m < NN) {
        unsigned long long* o =
            (unsigned long long*)(g_g2 + (size_t)m * DOUT + q * 16);
#pragma unroll
        for (int j = 0; j < 8; j++) o[j] = acc2[j];
    }
}

// =================== layer 2 aggregate + epilogue ===================
// out[n] = (g2[n] + sum g2[src]) / (deg+1) + b2
__global__ void spmm2_kernel(const float* __restrict__ b2,
                             float* __restrict__ out) {
    int w = (blockIdx.x * blockDim.x + threadIdx.x) >> 5;
    int lane = threadIdx.x & 31;
    if (w >= NN) return;
    int beg = g_rs[w], end = g_rs[w + 1];
    const float2* g4 = (const float2*)g_g2;
    float2 acc = g4[w * 32 + lane];   // self term
    int e = beg;
    for (; e + 4 <= end; e += 4) {
        int s0 = g_eord[e], s1 = g_eord[e + 1];
        int s2 = g_eord[e + 2], s3 = g_eord[e + 3];
        float2 v0 = __ldg(&g4[s0 * 32 + lane]);
        float2 v1 = __ldg(&g4[s1 * 32 + lane]);
        float2 v2 = __ldg(&g4[s2 * 32 + lane]);
        float2 v3 = __ldg(&g4[s3 * 32 + lane]);
        acc.x += (v0.x + v1.x) + (v2.x + v3.x);
        acc.y += (v0.y + v1.y) + (v2.y + v3.y);
    }
    for (; e < end; e++) {
        int s = g_eord[e];
        float2 v = __ldg(&g4[s * 32 + lane]);
        acc.x += v.x; acc.y += v.y;
    }
    float inv = 1.0f / (float)(end - beg + 1);
    float2 bb = ((const float2*)b2)[lane];
    float2 r;
    r.x = acc.x * inv + bb.x;
    r.y = acc.y * inv + bb.y;
    ((float2*)out)[w * 32 + lane] = r;
}

// =================== launch ===================
extern "C" void kernel_launch(void* const* d_in, const int* in_sizes, int n_in,
                              void* d_out, int out_size) {
    const float* feat = (const float*)d_in[0];
    const float* W1   = (const float*)d_in[1];
    const float* b1   = (const float*)d_in[2];
    const float* W2   = (const float*)d_in[3];
    const float* b2   = (const float*)d_in[4];
    const int*   src  = (const int*)d_in[5];
    const int*   dst  = (const int*)d_in[6];
    float* out = (float*)d_out;

    const int smem = (DIN * DH + DH * DOUT + 64 * 129) * (int)sizeof(float); // 131,328
    cudaFuncSetAttribute(gemm_fused_kernel,
                         cudaFuncAttributeMaxDynamicSharedMemorySize, smem);

    // CSR build
    zero_cnt_kernel<<<(NN + 255) / 256, 256>>>();
    hist_kernel<<<1024, 256>>>(dst);
    scan_blocksums_kernel<<<NBLK, 1024>>>();
    scan_top_kernel<<<1, 128>>>();
    scan_final_kernel<<<NBLK, 1024>>>();
    permute_kernel<<<1024, 256>>>(src, dst);

    // layer 1 aggregate -> fused GEMMs -> layer 2 aggregate
    spmm1_kernel<<<NN / 8, 256>>>(feat);                  // 12500 blocks
    gemm_fused_kernel<<<(NN + 63) / 64, 256, smem>>>(W1, b1, W2);
    spmm2_kernel<<<NN / 8, 256>>>(b2, out);
}

// round 7
// speedup vs baseline: 1.6049x; 1.0620x over previous
#include <cuda_runtime.h>
#include <cuda_fp16.h>
#include <cstdint>

#define NN   100000
#define NE   1600000
#define DIN  128
#define DH   128
#define DOUT 64
#define NBLK 98          // ceil(NN/1024)

// -------- scratch (device globals: allocation-guard safe) --------
__device__ float  g_a1[(size_t)NN * DIN];    // (sum_neigh feat + feat)/(deg+1), fp32
__device__ __half g_feath[(size_t)NN * DIN]; // fp16 copy of feat (gather payload)
__device__ __half g_g2h[(size_t)NN * DOUT];  // h1 @ W2, fp16 (gather payload)
__device__ int    g_cnt[NN];
__device__ int    g_rs[NN + 1];
__device__ int    g_cur[NN];
__device__ int    g_eord[NE];                // src ids sorted by dst
__device__ int    g_bsum[NBLK];
__device__ int    g_boff[NBLK];

// -------- packed fp32x2 helpers --------
__device__ __forceinline__ unsigned long long pack2(float x) {
    unsigned long long r;
    asm("mov.b64 %0, {%1, %1};" : "=l"(r) : "r"(__float_as_uint(x)));
    return r;
}
__device__ __forceinline__ unsigned long long fma2(unsigned long long a,
                                                   unsigned long long b,
                                                   unsigned long long c) {
    unsigned long long d;
    asm("fma.rn.f32x2 %0, %1, %2, %3;" : "=l"(d) : "l"(a), "l"(b), "l"(c));
    return d;
}

// =================== feat -> fp16 copy ===================
__global__ void cvt_feat_kernel(const float* __restrict__ feat) {
    int stride = gridDim.x * blockDim.x;
    const float4* f4 = (const float4*)feat;
    uint2* o = (uint2*)g_feath;
    const int total = NN * DIN / 4;
    for (int i = blockIdx.x * blockDim.x + threadIdx.x; i < total; i += stride) {
        float4 v = f4[i];
        __half2 h0 = __floats2half2_rn(v.x, v.y);
        __half2 h1 = __floats2half2_rn(v.z, v.w);
        uint2 u;
        u.x = *(unsigned int*)&h0;
        u.y = *(unsigned int*)&h1;
        o[i] = u;
    }
}

// =================== CSR build ===================

__global__ void zero_cnt_kernel() {
    int i = blockIdx.x * blockDim.x + threadIdx.x;
    if (i < NN) g_cnt[i] = 0;
}

__global__ void hist_kernel(const int* __restrict__ dst) {
    int stride = gridDim.x * blockDim.x;
    for (int i = blockIdx.x * blockDim.x + threadIdx.x; i < NE; i += stride)
        atomicAdd(&g_cnt[dst[i]], 1);
}

__global__ void scan_blocksums_kernel() {
    __shared__ int ws[32];
    int t = threadIdx.x, b = blockIdx.x;
    int i = b * 1024 + t;
    int v = (i < NN) ? g_cnt[i] : 0;
    int lane = t & 31, w = t >> 5;
    int x = v;
#pragma unroll
    for (int o = 16; o > 0; o >>= 1) x += __shfl_down_sync(~0u, x, o);
    if (lane == 0) ws[w] = x;
    __syncthreads();
    if (w == 0) {
        int y = ws[lane];
#pragma unroll
        for (int o = 16; o > 0; o >>= 1) y += __shfl_down_sync(~0u, y, o);
        if (lane == 0) g_bsum[b] = y;
    }
}

__global__ void scan_top_kernel() {
    __shared__ int s[NBLK];
    int t = threadIdx.x;
    if (t < NBLK) s[t] = g_bsum[t];
    __syncthreads();
    if (t == 0) {
        int run = 0;
        for (int i = 0; i < NBLK; i++) { int v = s[i]; s[i] = run; run += v; }
        g_rs[NN] = NE;
    }
    __syncthreads();
    if (t < NBLK) g_boff[t] = s[t];
}

__global__ void scan_final_kernel() {
    __shared__ int ws[32];
    int t = threadIdx.x, b = blockIdx.x;
    int i = b * 1024 + t;
    int v = (i < NN) ? g_cnt[i] : 0;
    int lane = t & 31, w = t >> 5;
    int x = v;
#pragma unroll
    for (int o = 1; o < 32; o <<= 1) {
        int y = __shfl_up_sync(~0u, x, o);
        if (lane >= o) x += y;
    }
    if (lane == 31) ws[w] = x;
    __syncthreads();
    if (w == 0) {
        int y = ws[lane];
#pragma unroll
        for (int o = 1; o < 32; o <<= 1) {
            int z = __shfl_up_sync(~0u, y, o);
            if (lane >= o) y += z;
        }
        ws[lane] = y;
    }
    __syncthreads();
    int incl = x + (w > 0 ? ws[w - 1] : 0);
    int excl = incl - v + g_boff[b];
    if (i < NN) { g_rs[i] = excl; g_cur[i] = excl; }
}

__global__ void permute_kernel(const int* __restrict__ src,
                               const int* __restrict__ dst) {
    int stride = gridDim.x * blockDim.x;
    for (int e = blockIdx.x * blockDim.x + threadIdx.x; e < NE; e += stride) {
        int d = dst[e];
        int p = atomicAdd(&g_cur[d], 1);
        g_eord[p] = src[e];
    }
}

// =================== layer 1 aggregate: one warp per dst node ===================
// a1[n] = (feat[n] + sum_{e: dst=n} feat_h[src_e]) / (deg_n + 1)
// gather payload fp16 (256B/row), accumulate fp32, self term fp32.
__global__ void spmm1_kernel(const float* __restrict__ feat) {
    int w = (blockIdx.x * blockDim.x + threadIdx.x) >> 5;
    int lane = threadIdx.x & 31;
    if (w >= NN) return;
    int beg = g_rs[w], end = g_rs[w + 1];
    const uint2* fh = (const uint2*)g_feath;   // 4 halves per uint2; 32 uint2 per row
    float4 acc = __ldg(&((const float4*)feat)[w * 32 + lane]);  // self (fp32)
    int e = beg;
    for (; e + 4 <= end; e += 4) {
        int s0 = g_eord[e], s1 = g_eord[e + 1];
        int s2 = g_eord[e + 2], s3 = g_eord[e + 3];
        uint2 u0 = __ldg(&fh[s0 * 32 + lane]);
        uint2 u1 = __ldg(&fh[s1 * 32 + lane]);
        uint2 u2 = __ldg(&fh[s2 * 32 + lane]);
        uint2 u3 = __ldg(&fh[s3 * 32 + lane]);
#pragma unroll
        for (int j = 0; j < 4; j++) {
            uint2 u = (j == 0) ? u0 : (j == 1) ? u1 : (j == 2) ? u2 : u3;
            float2 f0 = __half22float2(*(__half2*)&u.x);
            float2 f1 = __half22float2(*(__half2*)&u.y);
            acc.x += f0.x; acc.y += f0.y; acc.z += f1.x; acc.w += f1.y;
        }
    }
    for (; e < end; e++) {
        int s = g_eord[e];
        uint2 u = __ldg(&fh[s * 32 + lane]);
        float2 f0 = __half22float2(*(__half2*)&u.x);
        float2 f1 = __half22float2(*(__half2*)&u.y);
        acc.x += f0.x; acc.y += f0.y; acc.z += f1.x; acc.w += f1.y;
    }
    float inv = 1.0f / (float)(end - beg + 1);
    acc.x *= inv; acc.y *= inv; acc.z *= inv; acc.w *= inv;
    ((float4*)g_a1)[w * 32 + lane] = acc;
}

// =================== fused GEMM: h1 = relu(a1@W1 + b1); g2h = fp16(h1@W2) =========
__global__ void gemm_fused_kernel(const float* __restrict__ W1,
                                  const float* __restrict__ b1,
                                  const float* __restrict__ W2) {
    extern __shared__ float sm[];
    float* W1s = sm;                       // 128*128
    float* W2s = sm + DIN * DH;            // 128*64
    float* xs  = W2s + DH * DOUT;          // 64*129
    const int tid = threadIdx.x;

    {   // stage W1, W2
        const float4* w4 = (const float4*)W1;
        float4* s4 = (float4*)W1s;
#pragma unroll
        for (int i = 0; i < 16; i++) s4[tid + 256 * i] = w4[tid + 256 * i];
        const float4* v4 = (const float4*)W2;
        float4* t4 = (float4*)W2s;
#pragma unroll
        for (int i = 0; i < 8; i++) t4[tid + 256 * i] = v4[tid + 256 * i];
    }
    const int m0 = blockIdx.x * 64;
    {   // stage a1 tile (already normalized, fp32)
        int nrow = tid >> 2;
        int kq = (tid & 3) << 5;
        int m = m0 + nrow;
        if (m < NN) {
            const float4* fr = (const float4*)(g_a1 + (size_t)m * DIN);
#pragma unroll
            for (int j = 0; j < 8; j++) {
                float4 v = fr[(kq >> 2) + j];
                float* p = &xs[nrow * 129 + kq + 4 * j];
                p[0] = v.x; p[1] = v.y; p[2] = v.z; p[3] = v.w;
            }
        }
    }
    __syncthreads();

    const int n = tid & 63;
    const int q = tid >> 6;
    const int m = m0 + n;

    // ---- phase 1: h1 cols q*32..q*32+31 ----
    unsigned long long acc[16];
#pragma unroll
    for (int j = 0; j < 16; j++) acc[j] = 0ull;
    {
        const float* xrow = &xs[n * 129];
#pragma unroll 2
        for (int k = 0; k < DIN; k++) {
            unsigned long long xx = pack2(xrow[k]);
            const float4* w4 = (const float4*)(W1s + k * DH + q * 32);
#pragma unroll
            for (int j = 0; j < 8; j++) {
                float4 wv = w4[j];
                unsigned long long w01, w23;
                asm("mov.b64 %0, {%1, %2};" : "=l"(w01)
                    : "r"(__float_as_uint(wv.x)), "r"(__float_as_uint(wv.y)));
                asm("mov.b64 %0, {%1, %2};" : "=l"(w23)
                    : "r"(__float_as_uint(wv.z)), "r"(__float_as_uint(wv.w)));
                acc[2 * j]     = fma2(xx, w01, acc[2 * j]);
                acc[2 * j + 1] = fma2(xx, w23, acc[2 * j + 1]);
            }
        }
    }
    __syncthreads();

    {   // bias + relu -> xs holds h1
        const float* bb = b1 + q * 32;
        float* hrow = &xs[n * 129 + q * 32];
#pragma unroll
        for (int j = 0; j < 16; j++) {
            unsigned int lo = (unsigned int)(acc[j] & 0xffffffffull);
            unsigned int hi = (unsigned int)(acc[j] >> 32);
            float f0 = __uint_as_float(lo) + bb[2 * j];
            float f1 = __uint_as_float(hi) + bb[2 * j + 1];
            hrow[2 * j]     = fmaxf(f0, 0.0f);
            hrow[2 * j + 1] = fmaxf(f1, 0.0f);
        }
    }
    __syncthreads();

    // ---- phase 2: g2 cols q*16..q*16+15, write fp16 ----
    unsigned long long acc2[8];
#pragma unroll
    for (int j = 0; j < 8; j++) acc2[j] = 0ull;
    {
        const float* xrow = &xs[n * 129];
#pragma unroll 2
        for (int k = 0; k < DH; k++) {
            unsigned long long xx = pack2(xrow[k]);
            const float4* w4 = (const float4*)(W2s + k * DOUT + q * 16);
#pragma unroll
            for (int j = 0; j < 4; j++) {
                float4 wv = w4[j];
                unsigned long long w01, w23;
                asm("mov.b64 %0, {%1, %2};" : "=l"(w01)
                    : "r"(__float_as_uint(wv.x)), "r"(__float_as_uint(wv.y)));
                asm("mov.b64 %0, {%1, %2};" : "=l"(w23)
                    : "r"(__float_as_uint(wv.z)), "r"(__float_as_uint(wv.w)));
                acc2[2 * j]     = fma2(xx, w01, acc2[2 * j]);
                acc2[2 * j + 1] = fma2(xx, w23, acc2[2 * j + 1]);
            }
        }
    }
    if (m < NN) {
        unsigned int h[8];
#pragma unroll
        for (int j = 0; j < 8; j++) {
            float f0 = __uint_as_float((unsigned int)(acc2[j] & 0xffffffffull));
            float f1 = __uint_as_float((unsigned int)(acc2[j] >> 32));
            __half2 hh = __floats2half2_rn(f0, f1);
            h[j] = *(unsigned int*)&hh;
        }
        uint4* o = (uint4*)(g_g2h + (size_t)m * DOUT + q * 16);
        o[0] = make_uint4(h[0], h[1], h[2], h[3]);
        o[1] = make_uint4(h[4], h[5], h[6], h[7]);
    }
}

// =================== layer 2 aggregate + epilogue ===================
// out[n] = (g2h[n] + sum g2h[src]) / (deg+1) + b2
__global__ void spmm2_kernel(const float* __restrict__ b2,
                             float* __restrict__ out) {
    int w = (blockIdx.x * blockDim.x + threadIdx.x) >> 5;
    int lane = threadIdx.x & 31;
    if (w >= NN) return;
    int beg = g_rs[w], end = g_rs[w + 1];
    const unsigned int* gh = (const unsigned int*)g_g2h;  // 1 half2 per lane, 32/row
    unsigned int su = gh[w * 32 + lane];                  // self
    float2 acc = __half22float2(*(__half2*)&su);
    int e = beg;
    for (; e + 4 <= end; e += 4) {
        int s0 = g_eord[e], s1 = g_eord[e + 1];
        int s2 = g_eord[e + 2], s3 = g_eord[e + 3];
        unsigned int u0 = __ldg(&gh[s0 * 32 + lane]);
        unsigned int u1 = __ldg(&gh[s1 * 32 + lane]);
        unsigned int u2 = __ldg(&gh[s2 * 32 + lane]);
        unsigned int u3 = __ldg(&gh[s3 * 32 + lane]);
        float2 f0 = __half22float2(*(__half2*)&u0);
        float2 f1 = __half22float2(*(__half2*)&u1);
        float2 f2 = __half22float2(*(__half2*)&u2);
        float2 f3 = __half22float2(*(__half2*)&u3);
        acc.x += (f0.x + f1.x) + (f2.x + f3.x);
        acc.y += (f0.y + f1.y) + (f2.y + f3.y);
    }
    for (; e < end; e++) {
        int s = g_eord[e];
        unsigned int u = __ldg(&gh[s * 32 + lane]);
        float2 f = __half22float2(*(__half2*)&u);
        acc.x += f.x; acc.y += f.y;
    }
    float inv = 1.0f / (float)(end - beg + 1);
    float2 bb = ((const float2*)b2)[lane];
    float2 r;
    r.x = acc.x * inv + bb.x;
    r.y = acc.y * inv + bb.y;
    ((float2*)out)[w * 32 + lane] = r;
}

// =================== launch ===================
extern "C" void kernel_launch(void* const* d_in, const int* in_sizes, int n_in,
                              void* d_out, int out_size) {
    const float* feat = (const float*)d_in[0];
    const float* W1   = (const float*)d_in[1];
    const float* b1   = (const float*)d_in[2];
    const float* W2   = (const float*)d_in[3];
    const float* b2   = (const float*)d_in[4];
    const int*   src  = (const int*)d_in[5];
    const int*   dst  = (const int*)d_in[6];
    float* out = (float*)d_out;

    const int smem = (DIN * DH + DH * DOUT + 64 * 129) * (int)sizeof(float); // 131,328
    cudaFuncSetAttribute(gemm_fused_kernel,
                         cudaFuncAttributeMaxDynamicSharedMemorySize, smem);

    // CSR build + fp16 feat copy
    zero_cnt_kernel<<<(NN + 255) / 256, 256>>>();
    hist_kernel<<<1024, 256>>>(dst);
    cvt_feat_kernel<<<2048, 256>>>(feat);
    scan_blocksums_kernel<<<NBLK, 1024>>>();
    scan_top_kernel<<<1, 128>>>();
    scan_final_kernel<<<NBLK, 1024>>>();
    permute_kernel<<<1024, 256>>>(src, dst);

    // layer 1 aggregate -> fused GEMMs -> layer 2 aggregate
    spmm1_kernel<<<NN / 8, 256>>>(feat);
    gemm_fused_kernel<<<(NN + 63) / 64, 256, smem>>>(W1, b1, W2);
    spmm2_kernel<<<NN / 8, 256>>>(b2, out);
}